// round 1
// baseline (speedup 1.0000x reference)
#include <cuda_runtime.h>
#include <cstdint>

// LSTM: T=1024, B=64, D=512, gates 4D=2048. Gate order i,f,g,o (flax).
// Persistent kernel: 128 CTAs x 512 threads. Each CTA owns 4 output dims
// (16 z-columns). Weights resident in SMEM; activations staged per step.
// Packed f32x2 FMA inner loop. Grid-wide sense barrier per step.

#define TS   1024
#define BB   64
#define DD   512
#define NCTA 128
#define NTHR 512

// double-buffered recurrent h state (device scratch; no allocation)
__device__ float g_hbuf[2][BB * DD];
__device__ unsigned g_count = 0;
__device__ volatile unsigned g_gen = 0;

__device__ __forceinline__ void fma2(unsigned long long& d,
                                     unsigned long long a,
                                     unsigned long long b) {
    asm volatile("fma.rn.f32x2 %0, %1, %2, %0;" : "+l"(d) : "l"(a), "l"(b));
}

__device__ __forceinline__ float sigf(float x) {
    return 1.0f / (1.0f + __expf(-x));
}

__device__ __forceinline__ void grid_barrier() {
    __threadfence();          // release: h stores visible at L2
    __syncthreads();
    if (threadIdx.x == 0) {
        unsigned my = g_gen;  // volatile read (safe: bump needs my arrival)
        __threadfence();
        unsigned a = atomicAdd(&g_count, 1u);
        if (a == NCTA - 1) {
            g_count = 0;
            __threadfence();
            g_gen = my + 1;
        } else {
            while (g_gen == my) { __nanosleep(64); }
        }
        __threadfence();      // acquire
    }
    __syncthreads();
}

extern "C" __global__ void __launch_bounds__(NTHR, 1)
lstm_persistent(const float* __restrict__ x,    // [T,B,D]
                const float* __restrict__ c0,   // [B,D]
                const float* __restrict__ h0,   // [B,D]
                const float* __restrict__ Wi,   // [D,4D] row-major
                const float* __restrict__ Wh,   // [D,4D] row-major
                const float* __restrict__ bias, // [4D]
                float* __restrict__ out,
                long long out_size) {
    extern __shared__ float smem[];
    float* a_s = smem;            // 64x512 floats = 131072 B (act stage)
    float* Ws  = smem + 32768;    // 16 cols x 1032 (padded) = 66048 B
    float* red = smem;            // overlays a_s: [8][64][17] partials

    const int tid = threadIdx.x;
    const int d0  = blockIdx.x * 4;   // 4 dims per CTA

    // ---- one-time: load this CTA's weight slice into SMEM (col-major) ----
    // local col c = gate*4 + dloc  ->  global z col = gate*512 + d0 + dloc
    for (int i = tid; i < 16 * 1024; i += NTHR) {
        int c = i >> 10, k = i & 1023;
        int zc = ((c >> 2) << 9) + d0 + (c & 3);
        float w = (k < 512) ? Wi[(size_t)k * 2048 + zc]
                            : Wh[(size_t)(k - 512) * 2048 + zc];
        Ws[c * 1032 + k] = w;
    }

    // ---- compute roles ----
    const int col   = tid & 15;        // z column within CTA
    const int chunk = (tid >> 4) & 7;  // k-chunk (64 k per chunk per half... 2 halves)
    const int bq    = tid >> 7;        // batch quarter (16 rows)

    // ---- elementwise roles (tid < 256): (batch, dim) pair ----
    const int eb  = tid >> 2;
    const int edl = tid & 3;
    float c_reg = 0.f, b_i = 0.f, b_f = 0.f, b_g = 0.f, b_o = 0.f;
    if (tid < 256) {
        int d = d0 + edl;
        c_reg = c0[eb * DD + d];
        b_i = bias[d];
        b_f = bias[512 + d];
        b_g = bias[1024 + d];
        b_o = bias[1536 + d];
    }

    // base pointers for the packed inner loop
    const ulonglong2* ap_base =
        (const ulonglong2*)a_s + (bq * 16) * 128 + chunk * 16;

    float4* as4 = (float4*)a_s;

    for (int t = 0; t < TS; ++t) {
        // ---- stage x_t [64,512] into SMEM (coalesced) ----
        const float4* xs = (const float4*)x + (size_t)t * 8192;
        __syncthreads();  // a_s free (red consumed / first iter after Ws fill)
        for (int i = tid; i < 8192; i += NTHR) as4[i] = xs[i];
        __syncthreads();

        unsigned long long acc[16];
#pragma unroll
        for (int b = 0; b < 16; ++b) acc[b] = 0ULL;

        // ---- half 0: x @ Wi (k = 0..511) ----
        {
            const ulonglong2* wp =
                (const ulonglong2*)(Ws + col * 1032 + chunk * 64);
#pragma unroll 4
            for (int kk = 0; kk < 16; ++kk) {
                ulonglong2 w = wp[kk];
#pragma unroll
                for (int b = 0; b < 16; ++b) {
                    ulonglong2 a = ap_base[b * 128 + kk];
                    fma2(acc[b], w.x, a.x);
                    fma2(acc[b], w.y, a.y);
                }
            }
        }
        __syncthreads();

        // ---- stage h (L2-coherent, bypass L1) ----
        const float4* hs = (t == 0) ? (const float4*)h0
                                    : (const float4*)(g_hbuf[t & 1]);
        for (int i = tid; i < 8192; i += NTHR) as4[i] = __ldcg(hs + i);
        __syncthreads();

        // ---- half 1: h @ Wh (k = 512..1023) ----
        {
            const ulonglong2* wp =
                (const ulonglong2*)(Ws + col * 1032 + 512 + chunk * 64);
#pragma unroll 4
            for (int kk = 0; kk < 16; ++kk) {
                ulonglong2 w = wp[kk];
#pragma unroll
                for (int b = 0; b < 16; ++b) {
                    ulonglong2 a = ap_base[b * 128 + kk];
                    fma2(acc[b], w.x, a.x);
                    fma2(acc[b], w.y, a.y);
                }
            }
        }
        __syncthreads();  // done reading a_s; red may overlay it

        // ---- store partials: red[chunk][brow][col], padded row 17 ----
#pragma unroll
        for (int b = 0; b < 16; ++b) {
            float2 p = *(float2*)&acc[b];
            red[(chunk * 64 + bq * 16 + b) * 17 + col] = p.x + p.y;
        }
        __syncthreads();

        // ---- reduce + gates + state update (threads 0..255) ----
        if (tid < 256) {
            float zi = b_i, zf = b_f, zg = b_g, zo = b_o;
#pragma unroll
            for (int ch = 0; ch < 8; ++ch) {
                const float* r = &red[(ch * 64 + eb) * 17 + edl];
                zi += r[0];
                zf += r[4];
                zg += r[8];
                zo += r[12];
            }
            float cc = sigf(zf) * c_reg + sigf(zi) * tanhf(zg);
            float hh = sigf(zo) * tanhf(cc);
            c_reg = cc;
            int d = d0 + edl;
            __stcg(&g_hbuf[(t + 1) & 1][eb * DD + d], hh);
            out[(size_t)t * 32768 + eb * DD + d] = hh;  // ys
            if (t == TS - 1 && out_size >= 33554432LL + 65536LL) {
                out[33554432 + eb * DD + d] = cc;          // cT
                out[33554432 + 32768 + eb * DD + d] = hh;  // hT
            }
        }

        if (t != TS - 1) grid_barrier();
    }
}

extern "C" void kernel_launch(void* const* d_in, const int* in_sizes, int n_in,
                              void* d_out, int out_size) {
    const float* x  = (const float*)d_in[0];
    const float* c0 = (const float*)d_in[1];
    const float* h0 = (const float*)d_in[2];
    const float* Wi = (const float*)d_in[3];
    const float* Wh = (const float*)d_in[4];
    const float* b  = (const float*)d_in[5];

    // a_s 131072 B + Ws 66048 B
    const int smem_bytes = 131072 + 66048;
    cudaFuncSetAttribute(lstm_persistent,
                         cudaFuncAttributeMaxDynamicSharedMemorySize,
                         smem_bytes);

    lstm_persistent<<<NCTA, NTHR, smem_bytes>>>(
        x, c0, h0, Wi, Wh, b, (float*)d_out, (long long)out_size);
}

// round 2
// speedup vs baseline: 1.2575x; 1.2575x over previous
#include <cuda_runtime.h>
#include <cstdint>

// LSTM T=1024, B=64, D=512. Persistent kernel, 128 CTAs x 512 threads.
// Each CTA owns 4 output dims (16 z-cols). Weights SMEM-resident (XOR-swizzled).
// Per step: 4 tiles (x/h x batch-halves), cp.async double-buffered pipeline.
// Thread tile: 2 cols x 4 batches per batch-half, f32x2 packed FMA.
// Split-phase grid barrier (arrive after h write, wait hidden behind x compute).

#define TS   1024
#define BB   64
#define DD   512
#define NCTA 128
#define NTHR 512

#define BUF_STRIDE 516                 // floats per activation row (129 16B units)
#define BUF_FLOATS (32 * BUF_STRIDE)   // 16512 floats = 66048 B per buffer
#define WS_FLOATS  16384               // 16 cols x 1024 k = 65536 B
#define RED_FLOATS 8192                // 8 chunks x 64 b x 16 cols = 32768 B

__device__ float g_hbuf[2][BB * DD];
__device__ unsigned g_count = 0;
__device__ volatile unsigned g_gen = 0;

__device__ __forceinline__ void fma2(unsigned long long& d,
                                     unsigned long long a,
                                     unsigned long long b) {
    asm volatile("fma.rn.f32x2 %0, %1, %2, %0;" : "+l"(d) : "l"(a), "l"(b));
}

__device__ __forceinline__ float sigf(float x) {
    return __fdividef(1.0f, 1.0f + __expf(-x));
}
__device__ __forceinline__ float tanhfast(float x) {
    float e = __expf(-2.0f * x);
    return __fdividef(1.0f - e, 1.0f + e);
}

__device__ __forceinline__ void cpa16(float* dst, const float* src) {
    unsigned s = (unsigned)__cvta_generic_to_shared(dst);
    asm volatile("cp.async.cg.shared.global [%0], [%1], 16;" :: "r"(s), "l"(src));
}
#define CPA_COMMIT() asm volatile("cp.async.commit_group;" ::: "memory")
#define CPA_WAIT1()  asm volatile("cp.async.wait_group 1;" ::: "memory")
#define CPA_WAIT0()  asm volatile("cp.async.wait_group 0;" ::: "memory")

// stage 32 rows x 512 floats (64KB) global -> smem (row stride 516)
__device__ __forceinline__ void pf_tile(float* dst, const float* gsrc) {
    int r  = threadIdx.x >> 4;   // 0..31
    int c0 = threadIdx.x & 15;
    const float* s = gsrc + r * 512;
    float* d = dst + r * BUF_STRIDE;
#pragma unroll
    for (int j = 0; j < 8; ++j) {
        int c = c0 + j * 16;     // 16B chunk 0..127
        cpa16(d + c * 4, s + c * 4);
    }
}

// one tile: 2 cols x 4 batches x 64 k (chunk) with f32x2 FMA
__device__ __forceinline__ void gemm_tile(const float* __restrict__ Ws,
                                          const float* __restrict__ buf,
                                          int ubase,             // 0 (x) or 128 (h)
                                          unsigned long long* acc, // [8]
                                          int cp, int bhq, int chunk) {
    const ulonglong2* wp0 = (const ulonglong2*)Ws + (2 * cp) * 256 + ubase + chunk * 16;
    const ulonglong2* wp1 = wp0 + 256;
    const ulonglong2* ap  = (const ulonglong2*)buf + bhq * 129 + chunk * 16;
#pragma unroll 4
    for (int kk = 0; kk < 16; ++kk) {
        int u = kk ^ cp;                 // bank-quad swizzle
        ulonglong2 w0 = wp0[u];
        ulonglong2 w1 = wp1[u];
#pragma unroll
        for (int bi = 0; bi < 4; ++bi) {
            ulonglong2 a = ap[bi * 1032 + kk];   // rows bhq + 8*bi
            fma2(acc[bi],     w0.x, a.x);
            fma2(acc[bi],     w0.y, a.y);
            fma2(acc[4 + bi], w1.x, a.x);
            fma2(acc[4 + bi], w1.y, a.y);
        }
    }
}

extern "C" __global__ void __launch_bounds__(NTHR, 1)
lstm_pipe(const float* __restrict__ x,    // [T,B,D]
          const float* __restrict__ c0,   // [B,D]
          const float* __restrict__ h0,   // [B,D]
          const float* __restrict__ Wi,   // [D,4D]
          const float* __restrict__ Wh,   // [D,4D]
          const float* __restrict__ bias, // [4D]
          float* __restrict__ out,
          long long out_size) {
    extern __shared__ float smem[];
    float* Ws   = smem;
    float* buf0 = smem + WS_FLOATS;
    float* buf1 = buf0 + BUF_FLOATS;
    float* red  = buf1 + BUF_FLOATS;

    const int tid = threadIdx.x;
    const int d0  = blockIdx.x * 4;

    // prologue: prefetch x tile 0 of t=0 while filling weights
    pf_tile(buf0, x);
    CPA_COMMIT();

    // weight fill: col c (=gate*4+dloc) x k(0..1023), XOR-swizzled 16B units
    for (int i = tid; i < 16 * 1024; i += NTHR) {
        int c = i >> 10, k = i & 1023;
        int zc = ((c >> 2) << 9) + d0 + (c & 3);
        float w = (k < 512) ? Wi[(size_t)k * 2048 + zc]
                            : Wh[(size_t)(k - 512) * 2048 + zc];
        int unit = (c << 8) + ((k >> 2) ^ ((c >> 1) & 7));
        Ws[unit * 4 + (k & 3)] = w;
    }

    // thread decode: warp = cp(3b) + bhq_lo(2b); per-warp-uniform: chunk, bhq_hi
    const int cp    = tid & 7;
    const int chunk = (tid >> 5) & 7;
    const int bhq   = ((tid >> 3) & 3) | ((tid >> 8) << 2);

    // gate/elementwise roles (tid < 256)
    const int eb  = tid >> 2;
    const int edl = tid & 3;
    float c_reg = 0.f, b_i = 0.f, b_f = 0.f, b_g = 0.f, b_o = 0.f;
    if (tid < 256) {
        int d = d0 + edl;
        c_reg = c0[eb * DD + d];
        b_i = bias[d];
        b_f = bias[512 + d];
        b_g = bias[1024 + d];
        b_o = bias[1536 + d];
    }

    unsigned gen0 = 0;
    if (tid == 0) gen0 = g_gen;   // relative epoch (graph-replay safe)

    __syncthreads();              // Ws ready

    for (int t = 0; t < TS; ++t) {
        const float* xt   = x + (size_t)t * 32768;
        const float* hsrc = (t == 0) ? h0 : g_hbuf[t & 1];

        unsigned long long accA[8], accB[8];
#pragma unroll
        for (int i = 0; i < 8; ++i) { accA[i] = 0ULL; accB[i] = 0ULL; }

        // prefetch x tile 1; compute x tile 0 (buf0)
        pf_tile(buf1, xt + 32 * 512);
        CPA_COMMIT();
        CPA_WAIT1();
        __syncthreads();
        gemm_tile(Ws, buf0, 0, accA, cp, bhq, chunk);
        __syncthreads();

        // barrier WAIT (hidden behind x0 compute); gates h prefetch
        if (t > 0) {
            if (tid == 0) {
                while ((unsigned)(g_gen - gen0) < (unsigned)t) __nanosleep(32);
                __threadfence();
            }
            __syncthreads();
        }

        // prefetch h tile 0 into buf0; compute x tile 1 (buf1)
        pf_tile(buf0, hsrc);
        CPA_COMMIT();
        CPA_WAIT1();
        __syncthreads();
        gemm_tile(Ws, buf1, 0, accB, cp, bhq, chunk);
        __syncthreads();

        // prefetch h tile 1 into buf1; compute h tile 0 (buf0)
        pf_tile(buf1, hsrc + 32 * 512);
        CPA_COMMIT();
        CPA_WAIT1();
        __syncthreads();
        gemm_tile(Ws, buf0, 128, accA, cp, bhq, chunk);
        __syncthreads();

        // prefetch x tile 0 of t+1 into buf0; compute h tile 1 (buf1)
        if (t < TS - 1) {
            pf_tile(buf0, x + (size_t)(t + 1) * 32768);
            CPA_COMMIT();
            CPA_WAIT1();
        } else {
            CPA_WAIT0();
        }
        __syncthreads();
        gemm_tile(Ws, buf1, 128, accB, cp, bhq, chunk);

        // write chunk partials: red[chunk][b][col]
#pragma unroll
        for (int h = 0; h < 2; ++h) {
            unsigned long long* ac = h ? accB : accA;
#pragma unroll
            for (int ci = 0; ci < 2; ++ci)
#pragma unroll
                for (int bi = 0; bi < 4; ++bi) {
                    float2 p = *(float2*)&ac[ci * 4 + bi];
                    int b = h * 32 + bhq + bi * 8;
                    red[(chunk * 64 + b) * 16 + 2 * cp + ci] = p.x + p.y;
                }
        }
        __syncthreads();

        // reduce + gates + state update (tid < 256)
        if (tid < 256) {
            float zi = b_i, zf = b_f, zg = b_g, zo = b_o;
#pragma unroll
            for (int ch = 0; ch < 8; ++ch) {
                const float* r = &red[(ch * 64 + eb) * 16 + edl];
                zi += r[0];
                zf += r[4];
                zg += r[8];
                zo += r[12];
            }
            float cc = sigf(zf) * c_reg + sigf(zi) * tanhfast(zg);
            float hh = sigf(zo) * tanhfast(cc);
            c_reg = cc;
            int d = d0 + edl;
            __stcg(&g_hbuf[(t + 1) & 1][eb * DD + d], hh);
            out[(size_t)t * 32768 + eb * DD + d] = hh;
            if (t == TS - 1 && out_size >= 33554432LL + 65536LL) {
                out[33554432 + eb * DD + d] = cc;
                out[33554432 + 32768 + eb * DD + d] = hh;
            }
        }

        // barrier ARRIVE (no wait here)
        if (t < TS - 1) {
            __threadfence();
            __syncthreads();
            if (tid == 0) {
                unsigned a = atomicAdd(&g_count, 1u);
                if (((a + 1u) & (NCTA - 1u)) == 0u) g_gen = g_gen + 1u;
            }
        }
    }
}

extern "C" void kernel_launch(void* const* d_in, const int* in_sizes, int n_in,
                              void* d_out, int out_size) {
    const float* x  = (const float*)d_in[0];
    const float* c0 = (const float*)d_in[1];
    const float* h0 = (const float*)d_in[2];
    const float* Wi = (const float*)d_in[3];
    const float* Wh = (const float*)d_in[4];
    const float* b  = (const float*)d_in[5];

    const int smem_bytes = (WS_FLOATS + 2 * BUF_FLOATS + RED_FLOATS) * 4; // 230400
    cudaFuncSetAttribute(lstm_pipe,
                         cudaFuncAttributeMaxDynamicSharedMemorySize,
                         smem_bytes);

    lstm_pipe<<<NCTA, NTHR, smem_bytes>>>(
        x, c0, h0, Wi, Wh, b, (float*)d_out, (long long)out_size);
}